// round 2
// baseline (speedup 1.0000x reference)
#include <cuda_runtime.h>
#include <cuda_fp16.h>

// LNCC, volumes (B=2, C=1, 192,192,192) fp32, kernel 5, zero padding.
// Normalizer is always 1/125 (separable 1/5 per axis, zeros outside).
//
// Plan: two streaming kernels.
//  K_zy: z-filter (in-thread, contiguous axis) + y-filter (sliding ring over
//        streamed y) -> writes 5-channel zy-filtered fp16 tensor.
//  K_x : streams x with a sliding ring over the 5 channels, computes NCC per
//        voxel and reduces to a scalar. No second intermediate tensor.
// Rings are per-thread private (smem, no block syncs). fp16 values are
// rounded BEFORE accumulation so ring add/subtract cancels exactly.

#define NN    192
#define NZ4   48                  // 192/4 z-groups per line
#define V     14155776            // 2*192^3
#define CHUNK 24                  // streamed-axis chunk per block
#define NCHK  8                   // 192/24 chunks
#define TPB   128
#define COLS  18432               // 2*192*48 columns
#define BPC   (COLS / TPB)        // 144 blocks per chunk

__device__ __align__(16) __half g_mid[5 * V];   // [c][b][x][y][z], c-stride V
__device__ double g_acc;

__global__ void k_init() { g_acc = 0.0; }

// 5-tap sliding window sums over p0..p7 -> 4 outputs.
__device__ __forceinline__ float4 win5(float p0, float p1, float p2, float p3,
                                       float p4, float p5, float p6, float p7) {
    float s0 = ((p0 + p1) + (p2 + p3)) + p4;
    float s1 = s0 - p0 + p5;
    float s2 = s1 - p1 + p6;
    float s3 = s2 - p2 + p7;
    return make_float4(s0, s1, s2, s3);
}

__device__ __forceinline__ uint2 packh4(float4 s) {
    union { uint2 u; __half2 h[2]; } pk;
    pk.h[0] = __floats2half2_rn(s.x, s.y);
    pk.h[1] = __floats2half2_rn(s.z, s.w);
    return pk.u;
}

__device__ __forceinline__ float4 unpackh4(uint2 u) {
    union { uint2 u; __half2 h[2]; } pk;
    pk.u = u;
    float2 a = __half22float2(pk.h[0]);
    float2 b = __half22float2(pk.h[1]);
    return make_float4(a.x, a.y, b.x, b.y);
}

// ---------------------------------------------------------------------------
// K_zy: thread owns column (b, x, z4) and streams y over one chunk.
// Per y-step: z-filter 5 product channels from raw (float4 vector window),
// push fp16-rounded slice into a 5-deep private ring, keep fp32 running sums,
// emit zy-filtered fp16 when the window is full.
// ---------------------------------------------------------------------------
__global__ void __launch_bounds__(TPB) k_zy(const float* __restrict__ I,
                                            const float* __restrict__ J) {
    __shared__ uint2 ring[5][5][TPB];           // [slot][ch][tid] = 25.6 KB

    int tid = threadIdx.x;
    int yc  = blockIdx.x / BPC;
    int cid = (blockIdx.x % BPC) * TPB + tid;   // column id
    int z4  = cid % NZ4;
    int xr  = cid / NZ4;
    int x   = xr % NN;
    int b   = xr / NN;
    int colbase = (b * NN + x) * NN;            // (colbase + y)*NN + z
    int y0 = yc * CHUNK;

    float acc[5][4];
#pragma unroll
    for (int c = 0; c < 5; c++)
#pragma unroll
        for (int j = 0; j < 4; j++) acc[c][j] = 0.f;

    const float4 zero4 = make_float4(0.f, 0.f, 0.f, 0.f);

    for (int t = 0; t < CHUNK + 4; t++) {
        int yy = y0 - 2 + t;
        float4 s[5];
        if ((unsigned)yy < (unsigned)NN) {
            int base = (colbase + yy) * NN + z4 * 4;
            const float4* pi = reinterpret_cast<const float4*>(I + base);
            const float4* pj = reinterpret_cast<const float4*>(J + base);
            float4 im = (z4 > 0)       ? pi[-1] : zero4;
            float4 ib = pi[0];
            float4 ip = (z4 < NZ4 - 1) ? pi[1]  : zero4;
            float4 jm = (z4 > 0)       ? pj[-1] : zero4;
            float4 jb = pj[0];
            float4 jp = (z4 < NZ4 - 1) ? pj[1]  : zero4;
            float i0 = im.z, i1 = im.w, i2 = ib.x, i3 = ib.y,
                  i4 = ib.z, i5 = ib.w, i6 = ip.x, i7 = ip.y;
            float j0 = jm.z, j1 = jm.w, j2 = jb.x, j3 = jb.y,
                  j4 = jb.z, j5 = jb.w, j6 = jp.x, j7 = jp.y;
            s[0] = win5(i0, i1, i2, i3, i4, i5, i6, i7);
            s[1] = win5(j0, j1, j2, j3, j4, j5, j6, j7);
            s[2] = win5(i0*i0, i1*i1, i2*i2, i3*i3, i4*i4, i5*i5, i6*i6, i7*i7);
            s[3] = win5(j0*j0, j1*j1, j2*j2, j3*j3, j4*j4, j5*j5, j6*j6, j7*j7);
            s[4] = win5(i0*j0, i1*j1, i2*j2, i3*j3, i4*j4, i5*j5, i6*j6, i7*j7);
        } else {
#pragma unroll
            for (int c = 0; c < 5; c++) s[c] = zero4;
        }

        int slot = t % 5;
        if (t >= 5) {
#pragma unroll
            for (int c = 0; c < 5; c++) {
                float4 o = unpackh4(ring[slot][c][tid]);   // value from t-5
                acc[c][0] -= o.x; acc[c][1] -= o.y;
                acc[c][2] -= o.z; acc[c][3] -= o.w;
            }
        }
#pragma unroll
        for (int c = 0; c < 5; c++) {
            uint2 p = packh4(s[c]);                        // round first
            ring[slot][c][tid] = p;
            float4 r = unpackh4(p);
            acc[c][0] += r.x; acc[c][1] += r.y;
            acc[c][2] += r.z; acc[c][3] += r.w;
        }

        if (t >= 4) {
            int yo = y0 + t - 4;                           // yo < 192 by chunking
            int off = (colbase + yo) * NN + z4 * 4;
#pragma unroll
            for (int c = 0; c < 5; c++) {
                float4 a = make_float4(acc[c][0], acc[c][1], acc[c][2], acc[c][3]);
                *reinterpret_cast<uint2*>(g_mid + c * V + off) = packh4(a);
            }
        }
    }
}

// ---------------------------------------------------------------------------
// K_x: thread owns column (b, y, z4) and streams x over one chunk.
// Per x-step: load 5 channels (8B each, coalesced along z), ring-update the
// 125-tap running sums, emit NCC when window full, reduce at the end.
// ---------------------------------------------------------------------------
__global__ void __launch_bounds__(TPB) k_x() {
    __shared__ uint2 ring[5][5][TPB];
    __shared__ float ws[TPB / 32];

    int tid = threadIdx.x;
    int xc  = blockIdx.x / BPC;
    int cid = (blockIdx.x % BPC) * TPB + tid;
    int z4  = cid % NZ4;
    int yr  = cid / NZ4;
    int y   = yr % NN;
    int b   = yr / NN;
    int x0  = xc * CHUNK;

    float acc[5][4];
#pragma unroll
    for (int c = 0; c < 5; c++)
#pragma unroll
        for (int j = 0; j < 4; j++) acc[c][j] = 0.f;

    float local = 0.f;
    const float inv = 1.0f / 125.0f;

    for (int t = 0; t < CHUNK + 4; t++) {
        int xx = x0 - 2 + t;
        uint2 v[5];
        if ((unsigned)xx < (unsigned)NN) {
            int off = ((b * NN + xx) * NN + y) * NN + z4 * 4;
#pragma unroll
            for (int c = 0; c < 5; c++)
                v[c] = *reinterpret_cast<const uint2*>(g_mid + c * V + off);
        } else {
#pragma unroll
            for (int c = 0; c < 5; c++) v[c] = make_uint2(0u, 0u);
        }

        int slot = t % 5;
        if (t >= 5) {
#pragma unroll
            for (int c = 0; c < 5; c++) {
                float4 o = unpackh4(ring[slot][c][tid]);
                acc[c][0] -= o.x; acc[c][1] -= o.y;
                acc[c][2] -= o.z; acc[c][3] -= o.w;
            }
        }
#pragma unroll
        for (int c = 0; c < 5; c++) {
            ring[slot][c][tid] = v[c];
            float4 r = unpackh4(v[c]);
            acc[c][0] += r.x; acc[c][1] += r.y;
            acc[c][2] += r.z; acc[c][3] += r.w;
        }

        if (t >= 4) {
#pragma unroll
            for (int j = 0; j < 4; j++) {
                float uI  = acc[0][j] * inv;
                float uJ  = acc[1][j] * inv;
                float mI2 = acc[2][j] * inv;
                float mJ2 = acc[3][j] * inv;
                float mIJ = acc[4][j] * inv;
                float cross = mIJ - uI * uJ;
                float vI = mI2 - uI * uI;
                float vJ = mJ2 - uJ * uJ;
                local += (cross * cross) / (vI * vJ + 1e-5f);
            }
        }
    }

    // block reduction (128 threads = 4 warps) -> double atomic
#pragma unroll
    for (int o = 16; o; o >>= 1)
        local += __shfl_down_sync(0xffffffffu, local, o);
    int lane = tid & 31, wid = tid >> 5;
    if (lane == 0) ws[wid] = local;
    __syncthreads();
    if (wid == 0) {
        float vv = (lane < TPB / 32) ? ws[lane] : 0.f;
#pragma unroll
        for (int o = 2; o; o >>= 1)
            vv += __shfl_down_sync(0xffffffffu, vv, o);
        if (lane == 0) atomicAdd(&g_acc, (double)vv);
    }
}

__global__ void k_fin(float* out) {
    out[0] = (float)(-g_acc / (double)V);
}

extern "C" void kernel_launch(void* const* d_in, const int* in_sizes, int n_in,
                              void* d_out, int out_size) {
    const float* pred = (const float*)d_in[0];
    const float* targ = (const float*)d_in[1];
    (void)in_sizes; (void)n_in; (void)out_size;

    k_init<<<1, 1>>>();
    k_zy<<<NCHK * BPC, TPB>>>(pred, targ);   // 1152 blocks
    k_x<<<NCHK * BPC, TPB>>>();              // 1152 blocks
    k_fin<<<1, 1>>>((float*)d_out);
}